// round 1
// baseline (speedup 1.0000x reference)
#include <cuda_runtime.h>
#include <cuda_bf16.h>
#include <math.h>

// Problem constants
constexpr int BB = 2;       // batch
constexpr int CC = 512;     // channels
constexpr int NN = 4096;    // spatial (64*64)
constexpr int DD = 64;      // qk dim

// Scratch (static __device__ — no runtime allocation)
__device__ float g_q  [(size_t)BB * DD * NN];   // [b][d][i]  (transposed q)
__device__ float g_k  [(size_t)BB * DD * NN];   // [b][d][j]
__device__ float g_v  [(size_t)BB * CC * NN];   // [b][c][j]
__device__ float g_att[(size_t)BB * NN * NN];   // [b][i][j]  134 MB

// ---------------------------------------------------------------------------
// Projection: out[b][r][j] = sum_c W[r][c] * x[b][c][j] + bias[r]
// 64x64 tile, BK=16, 4x4 microtile, 256 threads.
// which: 0 -> g_q, 1 -> g_k, 2 -> g_v
// ---------------------------------------------------------------------------
__global__ __launch_bounds__(256) void proj_kernel(
    const float* __restrict__ W, const float* __restrict__ bias,
    const float* __restrict__ x, int R, int which)
{
    const int jBase = blockIdx.x * 64;
    const int rBase = blockIdx.y * 64;
    const int b     = blockIdx.z;

    float* outg = (which == 0) ? g_q : (which == 1) ? g_k : g_v;
    const float* xb = x + (size_t)b * CC * NN;
    float* ob = outg + (size_t)b * R * NN;

    __shared__ float Ws[16][68];
    __shared__ float Xs[16][68];

    const int tid = threadIdx.x;
    const int tx = tid & 15, ty = tid >> 4;

    float acc[4][4] = {};

    for (int cb = 0; cb < CC; cb += 16) {
        {   // W tile: [64 r][16 c], one float4 per thread
            int r  = tid >> 2;
            int k4 = tid & 3;
            float4 w = *(const float4*)&W[(size_t)(rBase + r) * CC + cb + k4 * 4];
            Ws[k4*4+0][r] = w.x; Ws[k4*4+1][r] = w.y;
            Ws[k4*4+2][r] = w.z; Ws[k4*4+3][r] = w.w;
        }
        {   // X tile: [16 c][64 j], coalesced
            int kk = tid >> 4;
            int j4 = tid & 15;
            float4 v = *(const float4*)&xb[(size_t)(cb + kk) * NN + jBase + j4 * 4];
            *(float4*)&Xs[kk][j4 * 4] = v;
        }
        __syncthreads();
        #pragma unroll
        for (int kk = 0; kk < 16; kk++) {
            float4 a  = *(const float4*)&Ws[kk][ty * 4];
            float4 bb = *(const float4*)&Xs[kk][tx * 4];
            float am[4] = {a.x, a.y, a.z, a.w};
            float bn[4] = {bb.x, bb.y, bb.z, bb.w};
            #pragma unroll
            for (int m = 0; m < 4; m++)
                #pragma unroll
                for (int n = 0; n < 4; n++)
                    acc[m][n] += am[m] * bn[n];
        }
        __syncthreads();
    }

    #pragma unroll
    for (int m = 0; m < 4; m++) {
        int r = rBase + ty * 4 + m;
        float bs = bias[r];
        float4 o = make_float4(acc[m][0] + bs, acc[m][1] + bs,
                               acc[m][2] + bs, acc[m][3] + bs);
        *(float4*)&ob[(size_t)r * NN + jBase + tx * 4] = o;
    }
}

// ---------------------------------------------------------------------------
// Scores: att[b][i][j] = sum_d qT[b][d][i] * k[b][d][j]   (unscaled)
// 64x64 tile, full K=64 via 16-chunks, 4x4 microtile.
// ---------------------------------------------------------------------------
__global__ __launch_bounds__(256) void scores_kernel()
{
    const int jBase = blockIdx.x * 64;
    const int iBase = blockIdx.y * 64;
    const int b     = blockIdx.z;

    const float* qb = g_q + (size_t)b * DD * NN;
    const float* kb = g_k + (size_t)b * DD * NN;
    float* ab = g_att + (size_t)b * NN * NN;

    __shared__ float Qs[16][68];
    __shared__ float Ks[16][68];

    const int tid = threadIdx.x;
    const int tx = tid & 15, ty = tid >> 4;

    float acc[4][4] = {};

    for (int db = 0; db < DD; db += 16) {
        {
            int kk = tid >> 4;
            int i4 = tid & 15;
            float4 v = *(const float4*)&qb[(size_t)(db + kk) * NN + iBase + i4 * 4];
            *(float4*)&Qs[kk][i4 * 4] = v;
        }
        {
            int kk = tid >> 4;
            int j4 = tid & 15;
            float4 v = *(const float4*)&kb[(size_t)(db + kk) * NN + jBase + j4 * 4];
            *(float4*)&Ks[kk][j4 * 4] = v;
        }
        __syncthreads();
        #pragma unroll
        for (int kk = 0; kk < 16; kk++) {
            float4 a  = *(const float4*)&Qs[kk][ty * 4];
            float4 bb = *(const float4*)&Ks[kk][tx * 4];
            float am[4] = {a.x, a.y, a.z, a.w};
            float bn[4] = {bb.x, bb.y, bb.z, bb.w};
            #pragma unroll
            for (int m = 0; m < 4; m++)
                #pragma unroll
                for (int n = 0; n < 4; n++)
                    acc[m][n] += am[m] * bn[n];
        }
        __syncthreads();
    }

    #pragma unroll
    for (int m = 0; m < 4; m++) {
        int i = iBase + ty * 4 + m;
        *(float4*)&ab[(size_t)i * NN + jBase + tx * 4] =
            make_float4(acc[m][0], acc[m][1], acc[m][2], acc[m][3]);
    }
}

// ---------------------------------------------------------------------------
// Row softmax over att[b][row][:], N=4096, 256 threads, 16 elems/thread
// single global read + single global write (values held in registers)
// ---------------------------------------------------------------------------
__global__ __launch_bounds__(256) void softmax_kernel()
{
    const int row = blockIdx.x;
    const int b   = blockIdx.y;
    float* p = g_att + ((size_t)b * NN + row) * NN;

    const int tid = threadIdx.x;
    float4 v[4];
    float m = -INFINITY;
    #pragma unroll
    for (int t = 0; t < 4; t++) {
        v[t] = ((const float4*)p)[tid + t * 256];
        m = fmaxf(m, fmaxf(fmaxf(v[t].x, v[t].y), fmaxf(v[t].z, v[t].w)));
    }

    __shared__ float smax[8];
    __shared__ float ssum[8];

    #pragma unroll
    for (int o = 16; o > 0; o >>= 1) m = fmaxf(m, __shfl_xor_sync(~0u, m, o));
    if ((tid & 31) == 0) smax[tid >> 5] = m;
    __syncthreads();
    m = smax[0];
    #pragma unroll
    for (int w = 1; w < 8; w++) m = fmaxf(m, smax[w]);

    float s = 0.f;
    #pragma unroll
    for (int t = 0; t < 4; t++) {
        v[t].x = __expf(v[t].x - m);
        v[t].y = __expf(v[t].y - m);
        v[t].z = __expf(v[t].z - m);
        v[t].w = __expf(v[t].w - m);
        s += v[t].x + v[t].y + v[t].z + v[t].w;
    }
    #pragma unroll
    for (int o = 16; o > 0; o >>= 1) s += __shfl_xor_sync(~0u, s, o);
    if ((tid & 31) == 0) ssum[tid >> 5] = s;
    __syncthreads();
    s = 0.f;
    #pragma unroll
    for (int w = 0; w < 8; w++) s += ssum[w];
    float inv = 1.0f / s;

    #pragma unroll
    for (int t = 0; t < 4; t++) {
        v[t].x *= inv; v[t].y *= inv; v[t].z *= inv; v[t].w *= inv;
        ((float4*)p)[tid + t * 256] = v[t];
    }
}

// ---------------------------------------------------------------------------
// AV + epilogue: out[b][c][i] = gamma * sum_j v[b][c][j]*att[b][i][j] + x[b][c][i]
// 128x128 tile, BK(j)=16, 8x8 microtile, 256 threads.
// ---------------------------------------------------------------------------
__global__ __launch_bounds__(256) void av_kernel(
    const float* __restrict__ x, const float* __restrict__ gamma,
    float* __restrict__ out)
{
    const int iBase = blockIdx.x * 128;
    const int cBase = blockIdx.y * 128;
    const int b     = blockIdx.z;

    const float* vb = g_v   + (size_t)b * CC * NN;
    const float* ab = g_att + (size_t)b * NN * NN;

    __shared__ float Vs[16][132];
    __shared__ float As[16][132];

    const int tid = threadIdx.x;
    const int tx = tid & 15, ty = tid >> 4;

    float acc[8][8] = {};

    for (int jb = 0; jb < NN; jb += 16) {
        #pragma unroll
        for (int t = 0; t < 2; t++) {           // V tile [128 c][16 j]
            int idx = tid + t * 256;
            int c  = idx >> 2;
            int j4 = idx & 3;
            float4 f = *(const float4*)&vb[(size_t)(cBase + c) * NN + jb + j4 * 4];
            Vs[j4*4+0][c] = f.x; Vs[j4*4+1][c] = f.y;
            Vs[j4*4+2][c] = f.z; Vs[j4*4+3][c] = f.w;
        }
        #pragma unroll
        for (int t = 0; t < 2; t++) {           // att tile [128 i][16 j]
            int idx = tid + t * 256;
            int i  = idx >> 2;
            int j4 = idx & 3;
            float4 f = *(const float4*)&ab[(size_t)(iBase + i) * NN + jb + j4 * 4];
            As[j4*4+0][i] = f.x; As[j4*4+1][i] = f.y;
            As[j4*4+2][i] = f.z; As[j4*4+3][i] = f.w;
        }
        __syncthreads();
        #pragma unroll
        for (int jj = 0; jj < 16; jj++) {
            float4 a0 = *(const float4*)&Vs[jj][ty * 4];
            float4 a1 = *(const float4*)&Vs[jj][ty * 4 + 64];
            float4 b0 = *(const float4*)&As[jj][tx * 4];
            float4 b1 = *(const float4*)&As[jj][tx * 4 + 64];
            float am[8] = {a0.x,a0.y,a0.z,a0.w, a1.x,a1.y,a1.z,a1.w};
            float bn[8] = {b0.x,b0.y,b0.z,b0.w, b1.x,b1.y,b1.z,b1.w};
            #pragma unroll
            for (int m = 0; m < 8; m++)
                #pragma unroll
                for (int n = 0; n < 8; n++)
                    acc[m][n] += am[m] * bn[n];
        }
        __syncthreads();
    }

    const float g = gamma[0];
    const float* xb = x + (size_t)b * CC * NN;
    float* ob = out + (size_t)b * CC * NN;

    #pragma unroll
    for (int m = 0; m < 8; m++) {
        int c = cBase + ty * 4 + ((m < 4) ? m : 64 + (m - 4));
        size_t base = (size_t)c * NN;
        #pragma unroll
        for (int half = 0; half < 2; half++) {
            int i = iBase + tx * 4 + half * 64;
            float4 xv = *(const float4*)&xb[base + i];
            int n0 = half * 4;
            float4 o = make_float4(g * acc[m][n0+0] + xv.x,
                                   g * acc[m][n0+1] + xv.y,
                                   g * acc[m][n0+2] + xv.z,
                                   g * acc[m][n0+3] + xv.w);
            *(float4*)&ob[base + i] = o;
        }
    }
}

// ---------------------------------------------------------------------------
extern "C" void kernel_launch(void* const* d_in, const int* in_sizes, int n_in,
                              void* d_out, int out_size)
{
    (void)in_sizes; (void)n_in; (void)out_size;
    const float* x     = (const float*)d_in[0];
    const float* Wq    = (const float*)d_in[1];
    const float* bq    = (const float*)d_in[2];
    const float* Wk    = (const float*)d_in[3];
    const float* bk    = (const float*)d_in[4];
    const float* Wv    = (const float*)d_in[5];
    const float* bv    = (const float*)d_in[6];
    const float* gamma = (const float*)d_in[7];
    float* out = (float*)d_out;

    // q, k projections: [64 x N] each
    proj_kernel<<<dim3(NN/64, 1, BB), 256>>>(Wq, bq, x, DD, 0);
    proj_kernel<<<dim3(NN/64, 1, BB), 256>>>(Wk, bk, x, DD, 1);
    // v projection: [512 x N]
    proj_kernel<<<dim3(NN/64, CC/64, BB), 256>>>(Wv, bv, x, CC, 2);
    // scores = q^T k  -> g_att
    scores_kernel<<<dim3(NN/64, NN/64, BB), 256>>>();
    // row softmax in place
    softmax_kernel<<<dim3(NN, BB), 256>>>();
    // out = gamma * (att @ v^T) + x
    av_kernel<<<dim3(NN/128, CC/128, BB), 256>>>(x, gamma, out);
}

// round 4
// speedup vs baseline: 3.9294x; 3.9294x over previous
#include <cuda_runtime.h>
#include <cuda.h>
#include <cstdint>
#include <math.h>

// Problem constants
constexpr int BB = 2;       // batch
constexpr int CC = 512;     // channels
constexpr int NN = 4096;    // spatial (64*64)
constexpr int DD = 64;      // qk dim

// ---------------------------------------------------------------------------
// Scratch (static __device__ — no runtime allocation)
// ---------------------------------------------------------------------------
__device__ __align__(1024) float g_q  [(size_t)BB * NN * DD];   // [b][n][d] tf32
__device__ __align__(1024) float g_k  [(size_t)BB * NN * DD];   // [b][n][d] tf32
__device__ __align__(1024) float g_v  [(size_t)BB * CC * NN];   // [b][c][j] tf32
__device__ __align__(1024) float g_xT [(size_t)BB * NN * CC];   // [b][n][c] tf32
__device__ __align__(1024) float g_wr [(size_t)CC * CC];        // Wv tf32
__device__ __align__(1024) float g_att[(size_t)BB * NN * NN];   // [b][i][j]

// ---------------------------------------------------------------------------
// PTX helpers (base-ISA only: sm_90-level TMA/mbarrier + sm_80 mma.sync)
// ---------------------------------------------------------------------------
__device__ __forceinline__ uint32_t smem_to_u32(const void* p) {
    uint32_t a;
    asm("{ .reg .u64 t; cvta.to.shared.u64 t, %1; cvt.u32.u64 %0, t; }"
        : "=r"(a) : "l"(p));
    return a;
}
__device__ __forceinline__ float tf32r(float v) {
    uint32_t o;
    asm("cvt.rna.tf32.f32 %0, %1;" : "=r"(o) : "f"(v));
    return __uint_as_float(o);
}

#define MBARRIER_INIT(addr, cnt) \
    asm volatile("mbarrier.init.shared.b64 [%0], %1;" \
        :: "r"((uint32_t)(addr)), "r"((uint32_t)(cnt)) : "memory")
#define MBARRIER_EXPECT_TX(addr, bytes) \
    asm volatile("mbarrier.arrive.expect_tx.shared.b64 _, [%0], %1;" \
        :: "r"((uint32_t)(addr)), "r"((uint32_t)(bytes)) : "memory")
#define MBARRIER_ARRIVE(addr) \
    asm volatile("mbarrier.arrive.shared.b64 _, [%0];" \
        :: "r"((uint32_t)(addr)) : "memory")
#define MBARRIER_WAIT_PARITY(addr, parity) do { \
    uint32_t _m = (uint32_t)(addr); uint32_t _p = (uint32_t)(parity); uint32_t _d; \
    asm volatile("{\n\t.reg .pred p;\n\t" \
        "mbarrier.try_wait.parity.shared.b64 p, [%1], %2;\n\t" \
        "selp.b32 %0, 1, 0, p;\n\t}" : "=r"(_d) : "r"(_m), "r"(_p) : "memory"); \
    if (!_d) { \
        asm volatile("{\n\t.reg .pred P1;\n\tWL_%=:\n\t" \
            "mbarrier.try_wait.parity.shared.b64 P1, [%0], %1, 0x989680;\n\t" \
            "@P1 bra.uni WD_%=;\n\tbra.uni WL_%=;\n\tWD_%=:\n\t}" \
            :: "r"(_m), "r"(_p) : "memory"); \
    } } while (0)

#define TMA_LOAD_3D(smem_addr, tmap, cx, cy, cz, mbar) \
    asm volatile( \
        "cp.async.bulk.tensor.3d.shared::cta.global.tile.mbarrier::complete_tx::bytes " \
        "[%0], [%1, {%2, %3, %4}], [%5];" \
        :: "r"((uint32_t)(smem_addr)), "l"(tmap), \
           "r"((int32_t)(cx)), "r"((int32_t)(cy)), "r"((int32_t)(cz)), \
           "r"((uint32_t)(mbar)) : "memory")

#define LDSM_X4(r0, r1, r2, r3, addr) \
    asm volatile("ldmatrix.sync.aligned.m8n8.x4.shared.b16 {%0,%1,%2,%3}, [%4];" \
        : "=r"(r0), "=r"(r1), "=r"(r2), "=r"(r3) : "r"(addr))

__device__ __forceinline__ void mma_tf32(float* d, const uint32_t* a, const uint32_t* b) {
    asm volatile(
        "mma.sync.aligned.m16n8k8.row.col.f32.tf32.tf32.f32 "
        "{%0,%1,%2,%3}, {%4,%5,%6,%7}, {%8,%9}, {%0,%1,%2,%3};"
        : "+f"(d[0]), "+f"(d[1]), "+f"(d[2]), "+f"(d[3])
        : "r"(a[0]), "r"(a[1]), "r"(a[2]), "r"(a[3]), "r"(b[0]), "r"(b[1]));
}

// ---------------------------------------------------------------------------
// Prep kernels
// ---------------------------------------------------------------------------
__global__ __launch_bounds__(256) void xT_round_kernel(const float* __restrict__ x)
{
    __shared__ float t[32][33];
    const int b  = blockIdx.z;
    const int n0 = blockIdx.x * 32, c0 = blockIdx.y * 32;
    const int tx = threadIdx.x & 31, ty = threadIdx.x >> 5;
    const float* xb = x + (size_t)b * CC * NN;
    #pragma unroll
    for (int i = 0; i < 32; i += 8)
        t[ty + i][tx] = xb[(size_t)(c0 + ty + i) * NN + n0 + tx];
    __syncthreads();
    float* o = g_xT + (size_t)b * NN * CC;
    #pragma unroll
    for (int i = 0; i < 32; i += 8)
        o[(size_t)(n0 + ty + i) * CC + c0 + tx] = tf32r(t[tx][ty + i]);
}

__global__ __launch_bounds__(256) void w_round_kernel(const float* __restrict__ W)
{
    int i = blockIdx.x * 256 + threadIdx.x;
    g_wr[i] = tf32r(W[i]);
}

// q/k projection (SIMT fp32, rounded output): out[b][n][d] = tf32(W x + b)
__global__ __launch_bounds__(256) void proj_qk_kernel(
    const float* __restrict__ W, const float* __restrict__ bias,
    const float* __restrict__ x, float* __restrict__ outT)
{
    const int jBase = blockIdx.x * 64;
    const int b     = blockIdx.z;
    const float* xb = x + (size_t)b * CC * NN;
    float* ob = outT + (size_t)b * NN * DD;

    __shared__ float Ws[16][68];
    __shared__ float Xs[16][68];
    const int tid = threadIdx.x;
    const int tx = tid & 15, ty = tid >> 4;
    float acc[4][4] = {};

    for (int cb = 0; cb < CC; cb += 16) {
        {
            int r = tid >> 2, k4 = tid & 3;
            float4 w = *(const float4*)&W[(size_t)r * CC + cb + k4 * 4];
            Ws[k4*4+0][r] = w.x; Ws[k4*4+1][r] = w.y;
            Ws[k4*4+2][r] = w.z; Ws[k4*4+3][r] = w.w;
        }
        {
            int kk = tid >> 4, j4 = tid & 15;
            *(float4*)&Xs[kk][j4 * 4] =
                *(const float4*)&xb[(size_t)(cb + kk) * NN + jBase + j4 * 4];
        }
        __syncthreads();
        #pragma unroll
        for (int kk = 0; kk < 16; kk++) {
            float4 a  = *(const float4*)&Ws[kk][ty * 4];
            float4 bb = *(const float4*)&Xs[kk][tx * 4];
            float am[4] = {a.x, a.y, a.z, a.w};
            float bn[4] = {bb.x, bb.y, bb.z, bb.w};
            #pragma unroll
            for (int m = 0; m < 4; m++)
                #pragma unroll
                for (int n = 0; n < 4; n++)
                    acc[m][n] += am[m] * bn[n];
        }
        __syncthreads();
    }
    #pragma unroll
    for (int m = 0; m < 4; m++) {
        int d = ty * 4 + m;
        float bs = bias[d];
        #pragma unroll
        for (int n = 0; n < 4; n++) {
            int j = jBase + tx * 4 + n;
            ob[(size_t)j * DD + d] = tf32r(acc[m][n] + bs);
        }
    }
}

// ---------------------------------------------------------------------------
// Unified TMA + mma.sync tf32 GEMM
// C[m][n] = sum_k A[m][k] * B[n][k]
// CTA tile 256(m) x 128(n) x 32(k); 16 compute warps (warp tile 64x32) + 1 producer.
// mode 0: proj_v (out = tf32(C + bias[m]))
// mode 1: AV     (out = gamma*C + x)
// mode 2: scores (out = C)
// ---------------------------------------------------------------------------
constexpr int BM = 256, BN = 128, BK = 32;
constexpr int NSTAGE = 3;
constexpr int A_BY = BM * BK * 4;                 // 32 KB
constexpr int B_BY = BN * BK * 4;                 // 16 KB
constexpr int STAGE_BY = A_BY + B_BY;             // 48 KB
constexpr int GEMM_DSMEM = NSTAGE * STAGE_BY + 1024;

__global__ __launch_bounds__(544)
void gemm_kernel(const __grid_constant__ CUtensorMap tma_a,
                 const __grid_constant__ CUtensorMap tma_b,
                 int k_total, int mode, int a_batched,
                 const float* __restrict__ aux,     // mode0: bias, mode1: x
                 const float* __restrict__ gamma,
                 float* __restrict__ outp, size_t out_bstride)
{
    __shared__ __align__(8) uint64_t s_bar[2 * NSTAGE];
    extern __shared__ char dsm[];
    const uint32_t dbase = (smem_to_u32(dsm) + 1023) & ~1023u;
    const uint32_t sbar  = smem_to_u32(s_bar);

    const int tid = threadIdx.x, wid = tid >> 5, lid = tid & 31;
    const int mBase = blockIdx.y * BM;
    const int nBase = blockIdx.x * BN;
    const int b     = blockIdx.z;
    const int nchunk = k_total / BK;

    if (tid == 0) {
        #pragma unroll
        for (int s = 0; s < NSTAGE; s++) {
            MBARRIER_INIT(sbar + s * 16, 1);        // full (tx-based)
            MBARRIER_INIT(sbar + s * 16 + 8, 16);   // empty (16 warps)
        }
    }
    __syncthreads();

    if (tid == 512) {
        // ---- producer ----
        const int az = a_batched ? b : 0;
        int ph = 1, st = 0;
        for (int c = 0; c < nchunk; c++) {
            MBARRIER_WAIT_PARITY(sbar + st * 16 + 8, ph);
            MBARRIER_EXPECT_TX(sbar + st * 16, STAGE_BY);
            TMA_LOAD_3D(dbase + st * STAGE_BY,        &tma_a, c * BK, mBase, az, sbar + st * 16);
            TMA_LOAD_3D(dbase + st * STAGE_BY + A_BY, &tma_b, c * BK, nBase, b,  sbar + st * 16);
            if (++st == NSTAGE) { st = 0; ph ^= 1; }
        }
    }

    if (wid < 16) {
        // ---- consumers ----
        const int wm = wid & 3, wn = wid >> 2;      // 4x4 warp grid
        const int mWarp = wm * 64, nWarp = wn * 32;

        const int laneA = lid & 15;                 // A row-in-16
        const int hAu   = (lid >> 4) & 1;           // A 16B half
        const int laneB = (lid & 7) + ((lid & 16) ? 8 : 0);
        const int hBu   = (lid >> 3) & 1;
        const int xor7  = lid & 7;

        float cacc[4][4][4] = {};

        int ph = 0, st = 0;
        for (int c = 0; c < nchunk; c++) {
            MBARRIER_WAIT_PARITY(sbar + st * 16, ph);
            const uint32_t Ab = dbase + st * STAGE_BY;
            const uint32_t Bb = Ab + A_BY;
            const uint32_t aRowAddr = Ab + (mWarp + laneA) * 128;
            const uint32_t bRowAddr = Bb + (nWarp + laneB) * 128;

            #pragma unroll
            for (int ks = 0; ks < BK / 8; ks++) {
                uint32_t af[4][4];
                uint32_t bf[4][2];
                const uint32_t cA = (uint32_t)(((2 * ks + hAu) ^ xor7) << 4);
                const uint32_t cB = (uint32_t)(((2 * ks + hBu) ^ xor7) << 4);
                #pragma unroll
                for (int mt = 0; mt < 4; mt++)
                    LDSM_X4(af[mt][0], af[mt][1], af[mt][2], af[mt][3],
                            aRowAddr + mt * (16 * 128) + cA);
                #pragma unroll
                for (int p = 0; p < 2; p++) {
                    uint32_t r0, r1, r2, r3;
                    LDSM_X4(r0, r1, r2, r3, bRowAddr + p * (16 * 128) + cB);
                    bf[2*p][0] = r0; bf[2*p][1] = r1;
                    bf[2*p+1][0] = r2; bf[2*p+1][1] = r3;
                }
                #pragma unroll
                for (int mt = 0; mt < 4; mt++)
                    #pragma unroll
                    for (int nt = 0; nt < 4; nt++)
                        mma_tf32(cacc[mt][nt], af[mt], bf[nt]);
            }
            if (lid == 0) MBARRIER_ARRIVE(sbar + st * 16 + 8);
            if (++st == NSTAGE) { st = 0; ph ^= 1; }
        }

        // ---- epilogue ----
        const int g = lid >> 2, t4 = lid & 3;
        float* ob = outp + (size_t)b * out_bstride;
        const float gm = (mode == 1) ? gamma[0] : 0.0f;

        #pragma unroll
        for (int mt = 0; mt < 4; mt++) {
            const int r0 = mBase + mWarp + mt * 16 + g;
            const int r1 = r0 + 8;
            float bias0 = 0.f, bias1 = 0.f;
            if (mode == 0) { bias0 = aux[r0]; bias1 = aux[r1]; }
            #pragma unroll
            for (int nt = 0; nt < 4; nt++) {
                const int col = nBase + nWarp + nt * 8 + t4 * 2;
                float v00 = cacc[mt][nt][0], v01 = cacc[mt][nt][1];
                float v10 = cacc[mt][nt][2], v11 = cacc[mt][nt][3];
                if (mode == 0) {
                    v00 = tf32r(v00 + bias0); v01 = tf32r(v01 + bias0);
                    v10 = tf32r(v10 + bias1); v11 = tf32r(v11 + bias1);
                } else if (mode == 1) {
                    const float2 x0 = *(const float2*)&aux[(size_t)b * out_bstride + (size_t)r0 * NN + col];
                    const float2 x1 = *(const float2*)&aux[(size_t)b * out_bstride + (size_t)r1 * NN + col];
                    v00 = gm * v00 + x0.x; v01 = gm * v01 + x0.y;
                    v10 = gm * v10 + x1.x; v11 = gm * v11 + x1.y;
                }
                *(float2*)&ob[(size_t)r0 * NN + col] = make_float2(v00, v01);
                *(float2*)&ob[(size_t)r1 * NN + col] = make_float2(v10, v11);
            }
        }
    }
}

// ---------------------------------------------------------------------------
// Row softmax (fp32 in, tf32-rounded out, in place)
// ---------------------------------------------------------------------------
__global__ __launch_bounds__(256) void softmax_kernel()
{
    const int row = blockIdx.x;
    const int b   = blockIdx.y;
    float* p = g_att + ((size_t)b * NN + row) * NN;

    const int tid = threadIdx.x;
    float4 v[4];
    float m = -INFINITY;
    #pragma unroll
    for (int t = 0; t < 4; t++) {
        v[t] = ((const float4*)p)[tid + t * 256];
        m = fmaxf(m, fmaxf(fmaxf(v[t].x, v[t].y), fmaxf(v[t].z, v[t].w)));
    }
    __shared__ float smax[8];
    __shared__ float ssum[8];
    #pragma unroll
    for (int o = 16; o > 0; o >>= 1) m = fmaxf(m, __shfl_xor_sync(~0u, m, o));
    if ((tid & 31) == 0) smax[tid >> 5] = m;
    __syncthreads();
    m = smax[0];
    #pragma unroll
    for (int w = 1; w < 8; w++) m = fmaxf(m, smax[w]);

    float s = 0.f;
    #pragma unroll
    for (int t = 0; t < 4; t++) {
        v[t].x = __expf(v[t].x - m); v[t].y = __expf(v[t].y - m);
        v[t].z = __expf(v[t].z - m); v[t].w = __expf(v[t].w - m);
        s += v[t].x + v[t].y + v[t].z + v[t].w;
    }
    #pragma unroll
    for (int o = 16; o > 0; o >>= 1) s += __shfl_xor_sync(~0u, s, o);
    if ((tid & 31) == 0) ssum[tid >> 5] = s;
    __syncthreads();
    s = 0.f;
    #pragma unroll
    for (int w = 0; w < 8; w++) s += ssum[w];
    const float inv = 1.0f / s;

    #pragma unroll
    for (int t = 0; t < 4; t++) {
        v[t].x = tf32r(v[t].x * inv); v[t].y = tf32r(v[t].y * inv);
        v[t].z = tf32r(v[t].z * inv); v[t].w = tf32r(v[t].w * inv);
        ((float4*)p)[tid + t * 256] = v[t];
    }
}

// ---------------------------------------------------------------------------
// Host side
// ---------------------------------------------------------------------------
typedef CUresult (*EncodeFn)(CUtensorMap*, CUtensorMapDataType, cuuint32_t, void*,
                             const cuuint64_t*, const cuuint64_t*, const cuuint32_t*,
                             const cuuint32_t*, CUtensorMapInterleave, CUtensorMapSwizzle,
                             CUtensorMapL2promotion, CUtensorMapFloatOOBfill);

static void build_tm(EncodeFn enc, CUtensorMap* tm, void* ptr,
                     uint64_t d0, uint64_t d1, uint64_t d2,
                     uint64_t s1b, uint64_t s2b, uint32_t b0, uint32_t b1)
{
    cuuint64_t dims[3] = {d0, d1, d2};
    cuuint64_t str[2]  = {s1b, s2b};
    cuuint32_t box[3]  = {b0, b1, 1};
    cuuint32_t es[3]   = {1, 1, 1};
    enc(tm, CU_TENSOR_MAP_DATA_TYPE_FLOAT32, 3, ptr, dims, str, box, es,
        CU_TENSOR_MAP_INTERLEAVE_NONE, CU_TENSOR_MAP_SWIZZLE_128B,
        CU_TENSOR_MAP_L2_PROMOTION_L2_128B, CU_TENSOR_MAP_FLOAT_OOB_FILL_NONE);
}

extern "C" void kernel_launch(void* const* d_in, const int* in_sizes, int n_in,
                              void* d_out, int out_size)
{
    (void)in_sizes; (void)n_in; (void)out_size;
    const float* x     = (const float*)d_in[0];
    const float* Wq    = (const float*)d_in[1];
    const float* bq    = (const float*)d_in[2];
    const float* Wk    = (const float*)d_in[3];
    const float* bk    = (const float*)d_in[4];
    const float* Wv    = (const float*)d_in[5];
    const float* bv    = (const float*)d_in[6];
    const float* gamma = (const float*)d_in[7];
    float* out = (float*)d_out;

    EncodeFn enc = nullptr;
    cudaDriverEntryPointQueryResult qr;
    cudaGetDriverEntryPointByVersion("cuTensorMapEncodeTiled", (void**)&enc, 12000,
                                     cudaEnableDefault, &qr);

    void *pq, *pk, *pv, *patt, *pxT, *pwr;
    cudaGetSymbolAddress(&pq,  g_q);
    cudaGetSymbolAddress(&pk,  g_k);
    cudaGetSymbolAddress(&pv,  g_v);
    cudaGetSymbolAddress(&patt, g_att);
    cudaGetSymbolAddress(&pxT, g_xT);
    cudaGetSymbolAddress(&pwr, g_wr);

    CUtensorMap tmQ, tmK, tmPA, tmPB, tmAA, tmAB;
    // scores: A = q [b][4096 rows][64], B = k (same shape)
    build_tm(enc, &tmQ, pq, DD, NN, BB, (uint64_t)DD * 4, (uint64_t)NN * DD * 4, 32, 256);
    build_tm(enc, &tmK, pk, DD, NN, BB, (uint64_t)DD * 4, (uint64_t)NN * DD * 4, 32, 128);
    // proj_v: A = Wr [512 rows][512], B = xT [b][4096 rows][512]
    build_tm(enc, &tmPA, pwr, CC, CC, 1,  (uint64_t)CC * 4, (uint64_t)CC * CC * 4, 32, 256);
    build_tm(enc, &tmPB, pxT, CC, NN, BB, (uint64_t)CC * 4, (uint64_t)NN * CC * 4, 32, 128);
    // AV: A = v [b][512 rows][4096], B = att [b][4096 rows][4096]
    build_tm(enc, &tmAA, pv,   NN, CC, BB, (uint64_t)NN * 4, (uint64_t)CC * NN * 4, 32, 256);
    build_tm(enc, &tmAB, patt, NN, NN, BB, (uint64_t)NN * 4, (uint64_t)NN * NN * 4, 32, 128);

    cudaFuncSetAttribute(gemm_kernel, cudaFuncAttributeMaxDynamicSharedMemorySize, GEMM_DSMEM);

    // 1. prep: transposed+rounded x, rounded Wv
    xT_round_kernel<<<dim3(NN / 32, CC / 32, BB), 256>>>(x);
    w_round_kernel<<<(CC * CC) / 256, 256>>>(Wv);
    // 2. q/k projections (SIMT, [n][d] tf32)
    proj_qk_kernel<<<dim3(NN / 64, 1, BB), 256>>>(Wq, bq, x, (float*)pq);
    proj_qk_kernel<<<dim3(NN / 64, 1, BB), 256>>>(Wk, bk, x, (float*)pk);
    // 3. v projection: C[c][n] = Wr·xT^T + bias, K=512
    gemm_kernel<<<dim3(NN / BN, CC / BM, BB), 544, GEMM_DSMEM>>>(
        tmPA, tmPB, CC, 0, 0, bv, gamma, (float*)pv, (size_t)CC * NN);
    // 4. scores: att[i][j] = q·k^T, K=64
    gemm_kernel<<<dim3(NN / BN, NN / BM, BB), 544, GEMM_DSMEM>>>(
        tmQ, tmK, DD, 2, 1, nullptr, gamma, (float*)patt, (size_t)NN * NN);
    // 5. softmax (in place, tf32-rounded)
    softmax_kernel<<<dim3(NN, BB), 256>>>();
    // 6. AV + epilogue: out = gamma*(v·att^T) + x, K=4096
    gemm_kernel<<<dim3(NN / BN, CC / BM, BB), 544, GEMM_DSMEM>>>(
        tmAA, tmAB, NN, 1, 1, x, gamma, out, (size_t)CC * NN);
}

// round 5
// speedup vs baseline: 4.3719x; 1.1126x over previous
#include <cuda_runtime.h>
#include <cuda.h>
#include <cstdint>
#include <math.h>

// Problem constants
constexpr int BB = 2;       // batch
constexpr int CC = 512;     // channels
constexpr int NN = 4096;    // spatial (64*64)
constexpr int DD = 64;      // qk dim
constexpr int QK = 128;     // stacked q|k dim

// ---------------------------------------------------------------------------
// Scratch (static __device__ — no runtime allocation)
// ---------------------------------------------------------------------------
__device__ __align__(1024) float g_qk [(size_t)BB * NN * QK];   // [b][n][q0..63|k64..127]
__device__ __align__(1024) float g_v  [(size_t)BB * CC * NN];   // [b][c][j] tf32
__device__ __align__(1024) float g_xT [(size_t)BB * NN * CC];   // [b][n][c] tf32
__device__ __align__(1024) float g_wr [(size_t)CC * CC];        // Wv tf32
__device__ __align__(1024) float g_wqk[(size_t)QK * CC];        // Wq|Wk tf32
__device__ __align__(1024) float g_bqk[QK];                     // bq|bk
__device__ __align__(1024) float g_att[(size_t)BB * NN * NN];   // [b][i][j]

// ---------------------------------------------------------------------------
// PTX helpers (base-ISA only: TMA/mbarrier + sm_80 mma.sync)
// ---------------------------------------------------------------------------
__device__ __forceinline__ uint32_t smem_to_u32(const void* p) {
    uint32_t a;
    asm("{ .reg .u64 t; cvta.to.shared.u64 t, %1; cvt.u32.u64 %0, t; }"
        : "=r"(a) : "l"(p));
    return a;
}
__device__ __forceinline__ float tf32r(float v) {
    uint32_t o;
    asm("cvt.rna.tf32.f32 %0, %1;" : "=r"(o) : "f"(v));
    return __uint_as_float(o);
}

#define MBARRIER_INIT(addr, cnt) \
    asm volatile("mbarrier.init.shared.b64 [%0], %1;" \
        :: "r"((uint32_t)(addr)), "r"((uint32_t)(cnt)) : "memory")
#define MBARRIER_EXPECT_TX(addr, bytes) \
    asm volatile("mbarrier.arrive.expect_tx.shared.b64 _, [%0], %1;" \
        :: "r"((uint32_t)(addr)), "r"((uint32_t)(bytes)) : "memory")
#define MBARRIER_ARRIVE(addr) \
    asm volatile("mbarrier.arrive.shared.b64 _, [%0];" \
        :: "r"((uint32_t)(addr)) : "memory")
#define MBARRIER_WAIT_PARITY(addr, parity) do { \
    uint32_t _m = (uint32_t)(addr); uint32_t _p = (uint32_t)(parity); uint32_t _d; \
    asm volatile("{\n\t.reg .pred p;\n\t" \
        "mbarrier.try_wait.parity.shared.b64 p, [%1], %2;\n\t" \
        "selp.b32 %0, 1, 0, p;\n\t}" : "=r"(_d) : "r"(_m), "r"(_p) : "memory"); \
    if (!_d) { \
        asm volatile("{\n\t.reg .pred P1;\n\tWL_%=:\n\t" \
            "mbarrier.try_wait.parity.shared.b64 P1, [%0], %1, 0x989680;\n\t" \
            "@P1 bra.uni WD_%=;\n\tbra.uni WL_%=;\n\tWD_%=:\n\t}" \
            :: "r"(_m), "r"(_p) : "memory"); \
    } } while (0)

#define TMA_LOAD_3D(smem_addr, tmap, cx, cy, cz, mbar) \
    asm volatile( \
        "cp.async.bulk.tensor.3d.shared::cta.global.tile.mbarrier::complete_tx::bytes " \
        "[%0], [%1, {%2, %3, %4}], [%5];" \
        :: "r"((uint32_t)(smem_addr)), "l"(tmap), \
           "r"((int32_t)(cx)), "r"((int32_t)(cy)), "r"((int32_t)(cz)), \
           "r"((uint32_t)(mbar)) : "memory")

#define LDSM_X4(r0, r1, r2, r3, addr) \
    asm volatile("ldmatrix.sync.aligned.m8n8.x4.shared.b16 {%0,%1,%2,%3}, [%4];" \
        : "=r"(r0), "=r"(r1), "=r"(r2), "=r"(r3) : "r"(addr))

__device__ __forceinline__ void mma_tf32(float* d, const uint32_t* a, const uint32_t* b) {
    asm volatile(
        "mma.sync.aligned.m16n8k8.row.col.f32.tf32.tf32.f32 "
        "{%0,%1,%2,%3}, {%4,%5,%6,%7}, {%8,%9}, {%0,%1,%2,%3};"
        : "+f"(d[0]), "+f"(d[1]), "+f"(d[2]), "+f"(d[3])
        : "r"(a[0]), "r"(a[1]), "r"(a[2]), "r"(a[3]), "r"(b[0]), "r"(b[1]));
}

// ---------------------------------------------------------------------------
// Prep kernels
// ---------------------------------------------------------------------------
__global__ __launch_bounds__(256) void xT_round_kernel(const float* __restrict__ x)
{
    __shared__ float t[32][33];
    const int b  = blockIdx.z;
    const int n0 = blockIdx.x * 32, c0 = blockIdx.y * 32;
    const int tx = threadIdx.x & 31, ty = threadIdx.x >> 5;
    const float* xb = x + (size_t)b * CC * NN;
    #pragma unroll
    for (int i = 0; i < 32; i += 8)
        t[ty + i][tx] = xb[(size_t)(c0 + ty + i) * NN + n0 + tx];
    __syncthreads();
    float* o = g_xT + (size_t)b * NN * CC;
    #pragma unroll
    for (int i = 0; i < 32; i += 8)
        o[(size_t)(n0 + ty + i) * CC + c0 + tx] = tf32r(t[tx][ty + i]);
}

__global__ __launch_bounds__(256) void w_round_kernel(const float* __restrict__ W)
{
    int i = blockIdx.x * 256 + threadIdx.x;
    g_wr[i] = tf32r(W[i]);
}

// Stack Wq|Wk (rounded) and bq|bk
__global__ __launch_bounds__(256) void wqk_prep_kernel(
    const float* __restrict__ Wq, const float* __restrict__ bq,
    const float* __restrict__ Wk, const float* __restrict__ bk)
{
    int i = blockIdx.x * 256 + threadIdx.x;     // over 128*512
    int r = i >> 9, c = i & 511;
    g_wqk[i] = tf32r(r < DD ? Wq[(size_t)r * CC + c] : Wk[(size_t)(r - DD) * CC + c]);
    if (i < QK) g_bqk[i] = (i < DD) ? bq[i] : bk[i - DD];
}

// ---------------------------------------------------------------------------
// Unified TMA + mma.sync tf32 GEMM
// C[m][n] = sum_k A[m][k] * B[n][k]
// CTA tile 256(m) x 128(n) x 32(k); 16 compute warps + 1 producer.
// mode 0: out = tf32(C + bias[row])   (proj_v)
// mode 1: out = gamma*C + x           (AV)
// mode 2: out = C                     (scores)
// mode 3: out = tf32(C + bias[col])   (qk projection)
// ---------------------------------------------------------------------------
constexpr int BM = 256, BN = 128, BK = 32;
constexpr int NSTAGE = 3;
constexpr int A_BY = BM * BK * 4;                 // 32 KB
constexpr int B_BY = BN * BK * 4;                 // 16 KB
constexpr int STAGE_BY = A_BY + B_BY;             // 48 KB
constexpr int GEMM_DSMEM = NSTAGE * STAGE_BY + 1024;

__global__ __launch_bounds__(544)
void gemm_kernel(const __grid_constant__ CUtensorMap tma_a,
                 const __grid_constant__ CUtensorMap tma_b,
                 int k_total, int mode, int a_batched, int b_batched,
                 int a_koff, int b_koff,
                 const float* __restrict__ aux,     // mode0/3: bias, mode1: x
                 const float* __restrict__ gamma,
                 float* __restrict__ outp, size_t out_bstride, int out_rstride)
{
    __shared__ __align__(8) uint64_t s_bar[2 * NSTAGE];
    extern __shared__ char dsm[];
    const uint32_t dbase = (smem_to_u32(dsm) + 1023) & ~1023u;
    const uint32_t sbar  = smem_to_u32(s_bar);

    const int tid = threadIdx.x, wid = tid >> 5, lid = tid & 31;
    const int mBase = blockIdx.y * BM;
    const int nBase = blockIdx.x * BN;
    const int b     = blockIdx.z;
    const int nchunk = k_total / BK;

    if (tid == 0) {
        #pragma unroll
        for (int s = 0; s < NSTAGE; s++) {
            MBARRIER_INIT(sbar + s * 16, 1);        // full (tx-based)
            MBARRIER_INIT(sbar + s * 16 + 8, 16);   // empty (16 warps)
        }
    }
    __syncthreads();

    if (tid == 512) {
        // ---- producer ----
        const int az = a_batched ? b : 0;
        const int bz = b_batched ? b : 0;
        int ph = 1, st = 0;
        for (int c = 0; c < nchunk; c++) {
            MBARRIER_WAIT_PARITY(sbar + st * 16 + 8, ph);
            MBARRIER_EXPECT_TX(sbar + st * 16, STAGE_BY);
            TMA_LOAD_3D(dbase + st * STAGE_BY,        &tma_a, a_koff + c * BK, mBase, az, sbar + st * 16);
            TMA_LOAD_3D(dbase + st * STAGE_BY + A_BY, &tma_b, b_koff + c * BK, nBase, bz, sbar + st * 16);
            if (++st == NSTAGE) { st = 0; ph ^= 1; }
        }
    }

    if (wid < 16) {
        // ---- consumers ----
        const int wm = wid & 3, wn = wid >> 2;      // 4x4 warp grid
        const int mWarp = wm * 64, nWarp = wn * 32;

        const int laneA = lid & 15;
        const int hAu   = (lid >> 4) & 1;
        const int laneB = (lid & 7) + ((lid & 16) ? 8 : 0);
        const int hBu   = (lid >> 3) & 1;
        const int xor7  = lid & 7;

        float cacc[4][4][4] = {};

        int ph = 0, st = 0;
        for (int c = 0; c < nchunk; c++) {
            MBARRIER_WAIT_PARITY(sbar + st * 16, ph);
            const uint32_t Ab = dbase + st * STAGE_BY;
            const uint32_t Bb = Ab + A_BY;
            const uint32_t aRowAddr = Ab + (mWarp + laneA) * 128;
            const uint32_t bRowAddr = Bb + (nWarp + laneB) * 128;

            #pragma unroll
            for (int ks = 0; ks < BK / 8; ks++) {
                uint32_t af[4][4];
                uint32_t bf[4][2];
                const uint32_t cA = (uint32_t)(((2 * ks + hAu) ^ xor7) << 4);
                const uint32_t cB = (uint32_t)(((2 * ks + hBu) ^ xor7) << 4);
                #pragma unroll
                for (int mt = 0; mt < 4; mt++)
                    LDSM_X4(af[mt][0], af[mt][1], af[mt][2], af[mt][3],
                            aRowAddr + mt * (16 * 128) + cA);
                #pragma unroll
                for (int p = 0; p < 2; p++) {
                    uint32_t r0, r1, r2, r3;
                    LDSM_X4(r0, r1, r2, r3, bRowAddr + p * (16 * 128) + cB);
                    bf[2*p][0] = r0; bf[2*p][1] = r1;
                    bf[2*p+1][0] = r2; bf[2*p+1][1] = r3;
                }
                #pragma unroll
                for (int mt = 0; mt < 4; mt++)
                    #pragma unroll
                    for (int nt = 0; nt < 4; nt++)
                        mma_tf32(cacc[mt][nt], af[mt], bf[nt]);
            }
            if (lid == 0) MBARRIER_ARRIVE(sbar + st * 16 + 8);
            if (++st == NSTAGE) { st = 0; ph ^= 1; }
        }

        // ---- epilogue ----
        const int g = lid >> 2, t4 = lid & 3;
        float* ob = outp + (size_t)b * out_bstride;
        const float gm = (mode == 1) ? gamma[0] : 0.0f;

        #pragma unroll
        for (int mt = 0; mt < 4; mt++) {
            const int r0 = mBase + mWarp + mt * 16 + g;
            const int r1 = r0 + 8;
            float bias0 = 0.f, bias1 = 0.f;
            if (mode == 0) { bias0 = aux[r0]; bias1 = aux[r1]; }
            #pragma unroll
            for (int nt = 0; nt < 4; nt++) {
                const int col = nBase + nWarp + nt * 8 + t4 * 2;
                float v00 = cacc[mt][nt][0], v01 = cacc[mt][nt][1];
                float v10 = cacc[mt][nt][2], v11 = cacc[mt][nt][3];
                if (mode == 0) {
                    v00 = tf32r(v00 + bias0); v01 = tf32r(v01 + bias0);
                    v10 = tf32r(v10 + bias1); v11 = tf32r(v11 + bias1);
                } else if (mode == 1) {
                    const float2 x0 = *(const float2*)&aux[(size_t)b * out_bstride + (size_t)r0 * out_rstride + col];
                    const float2 x1 = *(const float2*)&aux[(size_t)b * out_bstride + (size_t)r1 * out_rstride + col];
                    v00 = gm * v00 + x0.x; v01 = gm * v01 + x0.y;
                    v10 = gm * v10 + x1.x; v11 = gm * v11 + x1.y;
                } else if (mode == 3) {
                    const float bc0 = aux[col], bc1 = aux[col + 1];
                    v00 = tf32r(v00 + bc0); v01 = tf32r(v01 + bc1);
                    v10 = tf32r(v10 + bc0); v11 = tf32r(v11 + bc1);
                }
                *(float2*)&ob[(size_t)r0 * out_rstride + col] = make_float2(v00, v01);
                *(float2*)&ob[(size_t)r1 * out_rstride + col] = make_float2(v10, v11);
            }
        }
    }
}

// ---------------------------------------------------------------------------
// Row softmax (fp32 in, tf32-rounded out, in place)
// ---------------------------------------------------------------------------
__global__ __launch_bounds__(256) void softmax_kernel()
{
    const int row = blockIdx.x;
    const int b   = blockIdx.y;
    float* p = g_att + ((size_t)b * NN + row) * NN;

    const int tid = threadIdx.x;
    float4 v[4];
    float m = -INFINITY;
    #pragma unroll
    for (int t = 0; t < 4; t++) {
        v[t] = ((const float4*)p)[tid + t * 256];
        m = fmaxf(m, fmaxf(fmaxf(v[t].x, v[t].y), fmaxf(v[t].z, v[t].w)));
    }
    __shared__ float smax[8];
    __shared__ float ssum[8];
    #pragma unroll
    for (int o = 16; o > 0; o >>= 1) m = fmaxf(m, __shfl_xor_sync(~0u, m, o));
    if ((tid & 31) == 0) smax[tid >> 5] = m;
    __syncthreads();
    m = smax[0];
    #pragma unroll
    for (int w = 1; w < 8; w++) m = fmaxf(m, smax[w]);

    float s = 0.f;
    #pragma unroll
    for (int t = 0; t < 4; t++) {
        v[t].x = __expf(v[t].x - m); v[t].y = __expf(v[t].y - m);
        v[t].z = __expf(v[t].z - m); v[t].w = __expf(v[t].w - m);
        s += v[t].x + v[t].y + v[t].z + v[t].w;
    }
    #pragma unroll
    for (int o = 16; o > 0; o >>= 1) s += __shfl_xor_sync(~0u, s, o);
    if ((tid & 31) == 0) ssum[tid >> 5] = s;
    __syncthreads();
    s = 0.f;
    #pragma unroll
    for (int w = 0; w < 8; w++) s += ssum[w];
    const float inv = 1.0f / s;

    #pragma unroll
    for (int t = 0; t < 4; t++) {
        v[t].x = tf32r(v[t].x * inv); v[t].y = tf32r(v[t].y * inv);
        v[t].z = tf32r(v[t].z * inv); v[t].w = tf32r(v[t].w * inv);
        ((float4*)p)[tid + t * 256] = v[t];
    }
}

// ---------------------------------------------------------------------------
// Host side
// ---------------------------------------------------------------------------
typedef CUresult (*EncodeFn)(CUtensorMap*, CUtensorMapDataType, cuuint32_t, void*,
                             const cuuint64_t*, const cuuint64_t*, const cuuint32_t*,
                             const cuuint32_t*, CUtensorMapInterleave, CUtensorMapSwizzle,
                             CUtensorMapL2promotion, CUtensorMapFloatOOBfill);

static void build_tm(EncodeFn enc, CUtensorMap* tm, void* ptr,
                     uint64_t d0, uint64_t d1, uint64_t d2,
                     uint64_t s1b, uint64_t s2b, uint32_t b0, uint32_t b1)
{
    cuuint64_t dims[3] = {d0, d1, d2};
    cuuint64_t str[2]  = {s1b, s2b};
    cuuint32_t box[3]  = {b0, b1, 1};
    cuuint32_t es[3]   = {1, 1, 1};
    enc(tm, CU_TENSOR_MAP_DATA_TYPE_FLOAT32, 3, ptr, dims, str, box, es,
        CU_TENSOR_MAP_INTERLEAVE_NONE, CU_TENSOR_MAP_SWIZZLE_128B,
        CU_TENSOR_MAP_L2_PROMOTION_L2_128B, CU_TENSOR_MAP_FLOAT_OOB_FILL_NONE);
}

extern "C" void kernel_launch(void* const* d_in, const int* in_sizes, int n_in,
                              void* d_out, int out_size)
{
    (void)in_sizes; (void)n_in; (void)out_size;
    const float* x     = (const float*)d_in[0];
    const float* Wq    = (const float*)d_in[1];
    const float* bq    = (const float*)d_in[2];
    const float* Wk    = (const float*)d_in[3];
    const float* bk    = (const float*)d_in[4];
    const float* Wv    = (const float*)d_in[5];
    const float* bv    = (const float*)d_in[6];
    const float* gamma = (const float*)d_in[7];
    float* out = (float*)d_out;

    EncodeFn enc = nullptr;
    cudaDriverEntryPointQueryResult qr;
    cudaGetDriverEntryPointByVersion("cuTensorMapEncodeTiled", (void**)&enc, 12000,
                                     cudaEnableDefault, &qr);

    void *pqk, *pv, *patt, *pxT, *pwr, *pwqk, *pbqk;
    cudaGetSymbolAddress(&pqk,  g_qk);
    cudaGetSymbolAddress(&pv,   g_v);
    cudaGetSymbolAddress(&patt, g_att);
    cudaGetSymbolAddress(&pxT,  g_xT);
    cudaGetSymbolAddress(&pwr,  g_wr);
    cudaGetSymbolAddress(&pwqk, g_wqk);
    cudaGetSymbolAddress(&pbqk, g_bqk);

    CUtensorMap tmXT_A, tmXT_B, tmWQK, tmWV, tmQKa, tmQKb, tmV, tmATT;
    // xT [b][4096][512]: as A (box 256 rows) for qk-proj, as B (box 128) for v-proj
    build_tm(enc, &tmXT_A, pxT, CC, NN, BB, (uint64_t)CC * 4, (uint64_t)NN * CC * 4, 32, 256);
    build_tm(enc, &tmXT_B, pxT, CC, NN, BB, (uint64_t)CC * 4, (uint64_t)NN * CC * 4, 32, 128);
    // wqk [128][512] as B
    build_tm(enc, &tmWQK, pwqk, CC, QK, 1, (uint64_t)CC * 4, (uint64_t)QK * CC * 4, 32, 128);
    // wr [512][512] as A
    build_tm(enc, &tmWV, pwr, CC, CC, 1, (uint64_t)CC * 4, (uint64_t)CC * CC * 4, 32, 256);
    // qk [b][4096][128]: as A (q part) and B (k part) for scores
    build_tm(enc, &tmQKa, pqk, QK, NN, BB, (uint64_t)QK * 4, (uint64_t)NN * QK * 4, 32, 256);
    build_tm(enc, &tmQKb, pqk, QK, NN, BB, (uint64_t)QK * 4, (uint64_t)NN * QK * 4, 32, 128);
    // v [b][512][4096] as A, att [b][4096][4096] as B
    build_tm(enc, &tmV,   pv,   NN, CC, BB, (uint64_t)NN * 4, (uint64_t)CC * NN * 4, 32, 256);
    build_tm(enc, &tmATT, patt, NN, NN, BB, (uint64_t)NN * 4, (uint64_t)NN * NN * 4, 32, 128);

    cudaFuncSetAttribute(gemm_kernel, cudaFuncAttributeMaxDynamicSharedMemorySize, GEMM_DSMEM);

    // 1. prep
    xT_round_kernel<<<dim3(NN / 32, CC / 32, BB), 256>>>(x);
    w_round_kernel<<<(CC * CC) / 256, 256>>>(Wv);
    wqk_prep_kernel<<<(QK * CC) / 256, 256>>>(Wq, bq, Wk, bk);
    // 2. qk projection: g_qk[n][d] = xT·wqk^T + bqk[d], K=512
    gemm_kernel<<<dim3(QK / BN, NN / BM, BB), 544, GEMM_DSMEM>>>(
        tmXT_A, tmWQK, CC, 3, 1, 0, 0, 0, (const float*)pbqk, gamma,
        (float*)pqk, (size_t)NN * QK, QK);
    // 3. v projection: g_v[c][n] = wr·xT^T + bv[c], K=512
    gemm_kernel<<<dim3(NN / BN, CC / BM, BB), 544, GEMM_DSMEM>>>(
        tmWV, tmXT_B, CC, 0, 0, 1, 0, 0, bv, gamma,
        (float*)pv, (size_t)CC * NN, NN);
    // 4. scores: att[i][j] = q·k^T (q = qk cols 0-63, k = qk cols 64-127), K=64
    gemm_kernel<<<dim3(NN / BN, NN / BM, BB), 544, GEMM_DSMEM>>>(
        tmQKa, tmQKb, DD, 2, 1, 1, 0, DD, nullptr, gamma,
        (float*)patt, (size_t)NN * NN, NN);
    // 5. softmax (in place, tf32-rounded)
    softmax_kernel<<<dim3(NN, BB), 256>>>();
    // 6. AV + epilogue: out = gamma*(v·att^T) + x, K=4096
    gemm_kernel<<<dim3(NN / BN, CC / BM, BB), 544, GEMM_DSMEM>>>(
        tmV, tmATT, NN, 1, 1, 1, 0, 0, x, gamma,
        out, (size_t)CC * NN, NN);
}

// round 6
// speedup vs baseline: 4.8241x; 1.1034x over previous
#include <cuda_runtime.h>
#include <cuda.h>
#include <cstdint>
#include <math.h>

// Problem constants
constexpr int BB = 2;       // batch
constexpr int CC = 512;     // channels
constexpr int NN = 4096;    // spatial (64*64)
constexpr int DD = 64;      // qk dim
constexpr int QK = 128;     // stacked q|k dim

// ---------------------------------------------------------------------------
// Scratch (static __device__ — no runtime allocation)
// ---------------------------------------------------------------------------
__device__ __align__(1024) float g_qk [(size_t)BB * NN * QK];   // [b][n][q|k]
__device__ __align__(1024) float g_v  [(size_t)BB * CC * NN];   // [b][c][j] tf32
__device__ __align__(1024) float g_xT [(size_t)BB * NN * CC];   // [b][n][c] tf32
__device__ __align__(1024) float g_wr [(size_t)CC * CC];        // Wv tf32
__device__ __align__(1024) float g_wqk[(size_t)QK * CC];        // Wq|Wk tf32
__device__ __align__(1024) float g_bqk[QK];                     // bq|bk
__device__ __align__(1024) float g_att[(size_t)BB * NN * NN];   // [b][i][j] = exp(s)
__device__ __align__(1024) float g_rs [(size_t)BB * NN];        // row sums of exp

// ---------------------------------------------------------------------------
// PTX helpers (base-ISA only: TMA/mbarrier + sm_80 mma.sync)
// ---------------------------------------------------------------------------
__device__ __forceinline__ uint32_t smem_to_u32(const void* p) {
    uint32_t a;
    asm("{ .reg .u64 t; cvta.to.shared.u64 t, %1; cvt.u32.u64 %0, t; }"
        : "=r"(a) : "l"(p));
    return a;
}
__device__ __forceinline__ float tf32r(float v) {
    uint32_t o;
    asm("cvt.rna.tf32.f32 %0, %1;" : "=r"(o) : "f"(v));
    return __uint_as_float(o);
}

#define MBARRIER_INIT(addr, cnt) \
    asm volatile("mbarrier.init.shared.b64 [%0], %1;" \
        :: "r"((uint32_t)(addr)), "r"((uint32_t)(cnt)) : "memory")
#define MBARRIER_EXPECT_TX(addr, bytes) \
    asm volatile("mbarrier.arrive.expect_tx.shared.b64 _, [%0], %1;" \
        :: "r"((uint32_t)(addr)), "r"((uint32_t)(bytes)) : "memory")
#define MBARRIER_ARRIVE(addr) \
    asm volatile("mbarrier.arrive.shared.b64 _, [%0];" \
        :: "r"((uint32_t)(addr)) : "memory")
#define MBARRIER_WAIT_PARITY(addr, parity) do { \
    uint32_t _m = (uint32_t)(addr); uint32_t _p = (uint32_t)(parity); uint32_t _d; \
    asm volatile("{\n\t.reg .pred p;\n\t" \
        "mbarrier.try_wait.parity.shared.b64 p, [%1], %2;\n\t" \
        "selp.b32 %0, 1, 0, p;\n\t}" : "=r"(_d) : "r"(_m), "r"(_p) : "memory"); \
    if (!_d) { \
        asm volatile("{\n\t.reg .pred P1;\n\tWL_%=:\n\t" \
            "mbarrier.try_wait.parity.shared.b64 P1, [%0], %1, 0x989680;\n\t" \
            "@P1 bra.uni WD_%=;\n\tbra.uni WL_%=;\n\tWD_%=:\n\t}" \
            :: "r"(_m), "r"(_p) : "memory"); \
    } } while (0)

#define TMA_LOAD_3D(smem_addr, tmap, cx, cy, cz, mbar) \
    asm volatile( \
        "cp.async.bulk.tensor.3d.shared::cta.global.tile.mbarrier::complete_tx::bytes " \
        "[%0], [%1, {%2, %3, %4}], [%5];" \
        :: "r"((uint32_t)(smem_addr)), "l"(tmap), \
           "r"((int32_t)(cx)), "r"((int32_t)(cy)), "r"((int32_t)(cz)), \
           "r"((uint32_t)(mbar)) : "memory")

#define LDSM_X4(r0, r1, r2, r3, addr) \
    asm volatile("ldmatrix.sync.aligned.m8n8.x4.shared.b16 {%0,%1,%2,%3}, [%4];" \
        : "=r"(r0), "=r"(r1), "=r"(r2), "=r"(r3) : "r"(addr))

__device__ __forceinline__ void mma_tf32(float* d, const uint32_t* a, const uint32_t* b) {
    asm volatile(
        "mma.sync.aligned.m16n8k8.row.col.f32.tf32.tf32.f32 "
        "{%0,%1,%2,%3}, {%4,%5,%6,%7}, {%8,%9}, {%0,%1,%2,%3};"
        : "+f"(d[0]), "+f"(d[1]), "+f"(d[2]), "+f"(d[3])
        : "r"(a[0]), "r"(a[1]), "r"(a[2]), "r"(a[3]), "r"(b[0]), "r"(b[1]));
}

// ---------------------------------------------------------------------------
// Prep kernels
// ---------------------------------------------------------------------------
__global__ __launch_bounds__(256) void xT_round_kernel(const float* __restrict__ x)
{
    __shared__ float t[32][33];
    const int b  = blockIdx.z;
    const int n0 = blockIdx.x * 32, c0 = blockIdx.y * 32;
    const int tx = threadIdx.x & 31, ty = threadIdx.x >> 5;
    const float* xb = x + (size_t)b * CC * NN;
    #pragma unroll
    for (int i = 0; i < 32; i += 8)
        t[ty + i][tx] = xb[(size_t)(c0 + ty + i) * NN + n0 + tx];
    __syncthreads();
    float* o = g_xT + (size_t)b * NN * CC;
    #pragma unroll
    for (int i = 0; i < 32; i += 8)
        o[(size_t)(n0 + ty + i) * CC + c0 + tx] = tf32r(t[tx][ty + i]);
}

__global__ __launch_bounds__(256) void w_round_kernel(const float* __restrict__ W)
{
    int i = blockIdx.x * 256 + threadIdx.x;
    g_wr[i] = tf32r(W[i]);
}

__global__ __launch_bounds__(256) void wqk_prep_kernel(
    const float* __restrict__ Wq, const float* __restrict__ bq,
    const float* __restrict__ Wk, const float* __restrict__ bk)
{
    int i = blockIdx.x * 256 + threadIdx.x;     // over 128*512
    int r = i >> 9, c = i & 511;
    g_wqk[i] = tf32r(r < DD ? Wq[(size_t)r * CC + c] : Wk[(size_t)(r - DD) * CC + c]);
    if (i < QK) g_bqk[i] = (i < DD) ? bq[i] : bk[i - DD];
}

__global__ __launch_bounds__(256) void zero_rs_kernel()
{
    g_rs[blockIdx.x * 256 + threadIdx.x] = 0.0f;
}

// ---------------------------------------------------------------------------
// Unified TMA + mma.sync tf32 GEMM
// C[m][n] = sum_k A[m][k] * B[n][k]
// CTA tile 256(m) x 128(n) x 32(k); 16 compute warps + 1 producer.
// mode 0: out = tf32(C + bias[row])                 (proj_v)
// mode 1: out = gamma*C/rowsum[col] + x             (AV + normalize)
// mode 2: out = tf32(exp(C)); rowsum[row] += e      (scores + exp + rowsum)
// mode 3: out = tf32(C + bias[col])                 (qk projection)
// ---------------------------------------------------------------------------
constexpr int BM = 256, BN = 128, BK = 32;
constexpr int NSTAGE = 3;
constexpr int A_BY = BM * BK * 4;                 // 32 KB
constexpr int B_BY = BN * BK * 4;                 // 16 KB
constexpr int STAGE_BY = A_BY + B_BY;             // 48 KB
constexpr int GEMM_DSMEM = NSTAGE * STAGE_BY + 1024;

__global__ __launch_bounds__(544)
void gemm_kernel(const __grid_constant__ CUtensorMap tma_a,
                 const __grid_constant__ CUtensorMap tma_b,
                 int k_total, int mode, int a_batched, int b_batched,
                 int a_koff, int b_koff, int swap_xy,
                 const float* __restrict__ aux,     // mode0/3: bias, mode1: x
                 float* __restrict__ rs,            // mode1: read, mode2: atomic
                 const float* __restrict__ gamma,
                 float* __restrict__ outp, size_t out_bstride, int out_rstride)
{
    __shared__ __align__(8) uint64_t s_bar[2 * NSTAGE];
    extern __shared__ char dsm[];
    const uint32_t dbase = (smem_to_u32(dsm) + 1023) & ~1023u;
    const uint32_t sbar  = smem_to_u32(s_bar);

    const int tid = threadIdx.x, wid = tid >> 5, lid = tid & 31;
    const int mBase = (swap_xy ? blockIdx.x : blockIdx.y) * BM;
    const int nBase = (swap_xy ? blockIdx.y : blockIdx.x) * BN;
    const int b     = blockIdx.z;
    const int nchunk = k_total / BK;

    if (tid == 0) {
        #pragma unroll
        for (int s = 0; s < NSTAGE; s++) {
            MBARRIER_INIT(sbar + s * 16, 1);        // full (tx-based)
            MBARRIER_INIT(sbar + s * 16 + 8, 16);   // empty (16 warps)
        }
    }
    __syncthreads();

    if (tid == 512) {
        // ---- producer ----
        const int az = a_batched ? b : 0;
        const int bz = b_batched ? b : 0;
        int ph = 1, st = 0;
        for (int c = 0; c < nchunk; c++) {
            MBARRIER_WAIT_PARITY(sbar + st * 16 + 8, ph);
            MBARRIER_EXPECT_TX(sbar + st * 16, STAGE_BY);
            TMA_LOAD_3D(dbase + st * STAGE_BY,        &tma_a, a_koff + c * BK, mBase, az, sbar + st * 16);
            TMA_LOAD_3D(dbase + st * STAGE_BY + A_BY, &tma_b, b_koff + c * BK, nBase, bz, sbar + st * 16);
            if (++st == NSTAGE) { st = 0; ph ^= 1; }
        }
    }

    if (wid < 16) {
        // ---- consumers ----
        const int wm = wid & 3, wn = wid >> 2;      // 4x4 warp grid
        const int mWarp = wm * 64, nWarp = wn * 32;

        const int laneA = lid & 15;
        const int hAu   = (lid >> 4) & 1;
        const int laneB = (lid & 7) + ((lid & 16) ? 8 : 0);
        const int hBu   = (lid >> 3) & 1;
        const int xor7  = lid & 7;

        float cacc[4][4][4] = {};

        int ph = 0, st = 0;
        for (int c = 0; c < nchunk; c++) {
            MBARRIER_WAIT_PARITY(sbar + st * 16, ph);
            const uint32_t Ab = dbase + st * STAGE_BY;
            const uint32_t Bb = Ab + A_BY;
            const uint32_t aRowAddr = Ab + (mWarp + laneA) * 128;
            const uint32_t bRowAddr = Bb + (nWarp + laneB) * 128;

            #pragma unroll
            for (int ks = 0; ks < BK / 8; ks++) {
                uint32_t af[4][4];
                uint32_t bf[4][2];
                const uint32_t cA = (uint32_t)(((2 * ks + hAu) ^ xor7) << 4);
                const uint32_t cB = (uint32_t)(((2 * ks + hBu) ^ xor7) << 4);
                #pragma unroll
                for (int mt = 0; mt < 4; mt++)
                    LDSM_X4(af[mt][0], af[mt][1], af[mt][2], af[mt][3],
                            aRowAddr + mt * (16 * 128) + cA);
                #pragma unroll
                for (int p = 0; p < 2; p++) {
                    uint32_t r0, r1, r2, r3;
                    LDSM_X4(r0, r1, r2, r3, bRowAddr + p * (16 * 128) + cB);
                    bf[2*p][0] = r0; bf[2*p][1] = r1;
                    bf[2*p+1][0] = r2; bf[2*p+1][1] = r3;
                }
                #pragma unroll
                for (int mt = 0; mt < 4; mt++)
                    #pragma unroll
                    for (int nt = 0; nt < 4; nt++)
                        mma_tf32(cacc[mt][nt], af[mt], bf[nt]);
            }
            if (lid == 0) MBARRIER_ARRIVE(sbar + st * 16 + 8);
            if (++st == NSTAGE) { st = 0; ph ^= 1; }
        }

        // ---- epilogue ----
        const int g = lid >> 2, t4 = lid & 3;
        float* ob = outp + (size_t)b * out_bstride;
        float* rs_b = rs + (size_t)b * NN;
        const float gm = (mode == 1) ? gamma[0] : 0.0f;

        #pragma unroll
        for (int mt = 0; mt < 4; mt++) {
            const int r0 = mBase + mWarp + mt * 16 + g;
            const int r1 = r0 + 8;
            float bias0 = 0.f, bias1 = 0.f;
            if (mode == 0) { bias0 = aux[r0]; bias1 = aux[r1]; }
            float s0 = 0.f, s1 = 0.f;      // mode 2 row partial sums
            #pragma unroll
            for (int nt = 0; nt < 4; nt++) {
                const int col = nBase + nWarp + nt * 8 + t4 * 2;
                float v00 = cacc[mt][nt][0], v01 = cacc[mt][nt][1];
                float v10 = cacc[mt][nt][2], v11 = cacc[mt][nt][3];
                if (mode == 0) {
                    v00 = tf32r(v00 + bias0); v01 = tf32r(v01 + bias0);
                    v10 = tf32r(v10 + bias1); v11 = tf32r(v11 + bias1);
                } else if (mode == 1) {
                    const float i0 = __fdividef(1.0f, rs_b[col]);
                    const float i1 = __fdividef(1.0f, rs_b[col + 1]);
                    const float2 x0 = *(const float2*)&aux[(size_t)b * out_bstride + (size_t)r0 * out_rstride + col];
                    const float2 x1 = *(const float2*)&aux[(size_t)b * out_bstride + (size_t)r1 * out_rstride + col];
                    v00 = gm * v00 * i0 + x0.x; v01 = gm * v01 * i1 + x0.y;
                    v10 = gm * v10 * i0 + x1.x; v11 = gm * v11 * i1 + x1.y;
                } else if (mode == 2) {
                    v00 = tf32r(__expf(v00)); v01 = tf32r(__expf(v01));
                    v10 = tf32r(__expf(v10)); v11 = tf32r(__expf(v11));
                    s0 += v00 + v01; s1 += v10 + v11;
                } else {    // mode 3
                    const float bc0 = aux[col], bc1 = aux[col + 1];
                    v00 = tf32r(v00 + bc0); v01 = tf32r(v01 + bc1);
                    v10 = tf32r(v10 + bc0); v11 = tf32r(v11 + bc1);
                }
                *(float2*)&ob[(size_t)r0 * out_rstride + col] = make_float2(v00, v01);
                *(float2*)&ob[(size_t)r1 * out_rstride + col] = make_float2(v10, v11);
            }
            if (mode == 2) {
                // reduce across the 4 lanes (t4) sharing these rows, then one atomic
                s0 += __shfl_xor_sync(0xFFFFFFFFu, s0, 1);
                s0 += __shfl_xor_sync(0xFFFFFFFFu, s0, 2);
                s1 += __shfl_xor_sync(0xFFFFFFFFu, s1, 1);
                s1 += __shfl_xor_sync(0xFFFFFFFFu, s1, 2);
                if (t4 == 0) {
                    atomicAdd(&rs_b[r0], s0);
                    atomicAdd(&rs_b[r1], s1);
                }
            }
        }
    }
}

// ---------------------------------------------------------------------------
// Host side
// ---------------------------------------------------------------------------
typedef CUresult (*EncodeFn)(CUtensorMap*, CUtensorMapDataType, cuuint32_t, void*,
                             const cuuint64_t*, const cuuint64_t*, const cuuint32_t*,
                             const cuuint32_t*, CUtensorMapInterleave, CUtensorMapSwizzle,
                             CUtensorMapL2promotion, CUtensorMapFloatOOBfill);

static void build_tm(EncodeFn enc, CUtensorMap* tm, void* ptr,
                     uint64_t d0, uint64_t d1, uint64_t d2,
                     uint64_t s1b, uint64_t s2b, uint32_t b0, uint32_t b1)
{
    cuuint64_t dims[3] = {d0, d1, d2};
    cuuint64_t str[2]  = {s1b, s2b};
    cuuint32_t box[3]  = {b0, b1, 1};
    cuuint32_t es[3]   = {1, 1, 1};
    enc(tm, CU_TENSOR_MAP_DATA_TYPE_FLOAT32, 3, ptr, dims, str, box, es,
        CU_TENSOR_MAP_INTERLEAVE_NONE, CU_TENSOR_MAP_SWIZZLE_128B,
        CU_TENSOR_MAP_L2_PROMOTION_L2_128B, CU_TENSOR_MAP_FLOAT_OOB_FILL_NONE);
}

extern "C" void kernel_launch(void* const* d_in, const int* in_sizes, int n_in,
                              void* d_out, int out_size)
{
    (void)in_sizes; (void)n_in; (void)out_size;
    const float* x     = (const float*)d_in[0];
    const float* Wq    = (const float*)d_in[1];
    const float* bq    = (const float*)d_in[2];
    const float* Wk    = (const float*)d_in[3];
    const float* bk    = (const float*)d_in[4];
    const float* Wv    = (const float*)d_in[5];
    const float* bv    = (const float*)d_in[6];
    const float* gamma = (const float*)d_in[7];
    float* out = (float*)d_out;

    EncodeFn enc = nullptr;
    cudaDriverEntryPointQueryResult qr;
    cudaGetDriverEntryPointByVersion("cuTensorMapEncodeTiled", (void**)&enc, 12000,
                                     cudaEnableDefault, &qr);

    void *pqk, *pv, *patt, *pxT, *pwr, *pwqk, *pbqk, *prs;
    cudaGetSymbolAddress(&pqk,  g_qk);
    cudaGetSymbolAddress(&pv,   g_v);
    cudaGetSymbolAddress(&patt, g_att);
    cudaGetSymbolAddress(&pxT,  g_xT);
    cudaGetSymbolAddress(&pwr,  g_wr);
    cudaGetSymbolAddress(&pwqk, g_wqk);
    cudaGetSymbolAddress(&pbqk, g_bqk);
    cudaGetSymbolAddress(&prs,  g_rs);

    CUtensorMap tmXT_A, tmXT_B, tmWQK, tmWV, tmQKa, tmQKb, tmV, tmATT;
    build_tm(enc, &tmXT_A, pxT, CC, NN, BB, (uint64_t)CC * 4, (uint64_t)NN * CC * 4, 32, 256);
    build_tm(enc, &tmXT_B, pxT, CC, NN, BB, (uint64_t)CC * 4, (uint64_t)NN * CC * 4, 32, 128);
    build_tm(enc, &tmWQK, pwqk, CC, QK, 1, (uint64_t)CC * 4, (uint64_t)QK * CC * 4, 32, 128);
    build_tm(enc, &tmWV, pwr, CC, CC, 1, (uint64_t)CC * 4, (uint64_t)CC * CC * 4, 32, 256);
    build_tm(enc, &tmQKa, pqk, QK, NN, BB, (uint64_t)QK * 4, (uint64_t)NN * QK * 4, 32, 256);
    build_tm(enc, &tmQKb, pqk, QK, NN, BB, (uint64_t)QK * 4, (uint64_t)NN * QK * 4, 32, 128);
    build_tm(enc, &tmV,   pv,   NN, CC, BB, (uint64_t)NN * 4, (uint64_t)CC * NN * 4, 32, 256);
    build_tm(enc, &tmATT, patt, NN, NN, BB, (uint64_t)NN * 4, (uint64_t)NN * NN * 4, 32, 128);

    cudaFuncSetAttribute(gemm_kernel, cudaFuncAttributeMaxDynamicSharedMemorySize, GEMM_DSMEM);

    float* frs = (float*)prs;

    // 1. prep
    xT_round_kernel<<<dim3(NN / 32, CC / 32, BB), 256>>>(x);
    w_round_kernel<<<(CC * CC) / 256, 256>>>(Wv);
    wqk_prep_kernel<<<(QK * CC) / 256, 256>>>(Wq, bq, Wk, bk);
    zero_rs_kernel<<<(BB * NN) / 256, 256>>>();
    // 2. qk projection: g_qk[n][d] = xT·wqk^T + bqk[d], K=512
    gemm_kernel<<<dim3(QK / BN, NN / BM, BB), 544, GEMM_DSMEM>>>(
        tmXT_A, tmWQK, CC, 3, 1, 0, 0, 0, 0, (const float*)pbqk, frs, gamma,
        (float*)pqk, (size_t)NN * QK, QK);
    // 3. v projection: g_v[c][n] = wr·xT^T + bv[c], K=512
    gemm_kernel<<<dim3(NN / BN, CC / BM, BB), 544, GEMM_DSMEM>>>(
        tmWV, tmXT_B, CC, 0, 0, 1, 0, 0, 0, bv, frs, gamma,
        (float*)pv, (size_t)CC * NN, NN);
    // 4. scores + exp + rowsum: g_att[i][j] = tf32(exp(q·k)), K=64
    gemm_kernel<<<dim3(NN / BN, NN / BM, BB), 544, GEMM_DSMEM>>>(
        tmQKa, tmQKb, DD, 2, 1, 1, 0, DD, 0, nullptr, frs, gamma,
        (float*)patt, (size_t)NN * NN, NN);
    // 5. AV + normalize + epilogue: out = gamma*(v·e^T)/rowsum + x, K=4096
    //    swap_xy: consecutive CTAs share the e-tile -> L2 dedups the 134MB read
    gemm_kernel<<<dim3(CC / BM, NN / BN, BB), 544, GEMM_DSMEM>>>(
        tmV, tmATT, NN, 1, 1, 1, 0, 0, 1, x, frs, gamma,
        out, (size_t)CC * NN, NN);
}